// round 9
// baseline (speedup 1.0000x reference)
#include <cuda_runtime.h>
#include <cuda_bf16.h>

// MomentumLSTM v8: unit-pair accumulators — natural weight pairs (w_u0,w_u1) via
// LDS.64, h/x state stored DUPLICATED (h,h) and read two pairs per LDS.128.
// Zero pack/swap MOVs in the gate loops. Persistent 152x384, warp-local recurrence,
// HW tanh with 0.5-prescaled i/f/o rows.

#define BATCH  32768
#define TT     60
#define DD     7
#define H1     64
#define G1     256
#define H2     32
#define G2     128
#define NT     384
#define GRID   152
#define TB     8                 // batches per warp-task
#define NTASKS (BATCH / TB)      // 4096
#define WSLOTS (GRID * 12)       // 1824
#define HSTR   20                // dup-slab row stride (floats), 16B-aligned rows

// SMEM float offsets
#define OFF_W1T 0                // [71][256] rows 0..6 x-w, 7..70 h-w (i/f/o pre-scaled 0.5)
#define OFF_W2T 18176            // [96][128]
#define OFF_B1  30464            // [256]
#define OFF_B2  30720            // [128]
#define OFF_H1  30848            // 12 x [64][20] dup: row k, cols 2b,2b+1 = h1[k][b]
#define OFF_H2  46208            // 12 x [32][20] dup
#define OFF_X   53888            // 12 x [7][20] dup
#define SMEM_FLOATS 55568
#define SMEM_BYTES  (SMEM_FLOATS * 4)   // 222272

typedef unsigned long long u64t;

__device__ __forceinline__ u64t pk2(float a, float b) {
    u64t r; asm("mov.b64 %0, {%1, %2};" : "=l"(r) : "f"(a), "f"(b)); return r;
}
__device__ __forceinline__ void upk(u64t v, float& lo, float& hi) {
    asm("mov.b64 {%0, %1}, %2;" : "=f"(lo), "=f"(hi) : "l"(v));
}
__device__ __forceinline__ u64t fma2(u64t a, u64t b, u64t c) {
    u64t d; asm("fma.rn.f32x2 %0, %1, %2, %3;" : "=l"(d) : "l"(a), "l"(b), "l"(c)); return d;
}
__device__ __forceinline__ u64t lds64(const float* p) {
    return *reinterpret_cast<const u64t*>(p);
}
__device__ __forceinline__ void sts64(float* p, u64t v) {
    *reinterpret_cast<u64t*>(p) = v;
}
__device__ __forceinline__ ulonglong2 lds128(const float* p) {
    return *reinterpret_cast<const ulonglong2*>(p);
}
__device__ __forceinline__ void sts128(float* p, ulonglong2 v) {
    *reinterpret_cast<ulonglong2*>(p) = v;
}
__device__ __forceinline__ float tanha(float x) {
    float y; asm("tanh.approx.f32 %0, %1;" : "=f"(y) : "f"(x)); return y;
}
// acc already holds x/2 (weights pre-scaled): sigmoid(x) = 0.5*tanh(x/2)+0.5
__device__ __forceinline__ float sig_h(float halfx) {
    return fmaf(0.5f, tanha(halfx), 0.5f);
}
__device__ __forceinline__ float sigx(float x) {   // exact, output only
    return __fdividef(1.0f, 1.0f + __expf(-x));
}

__global__ void __launch_bounds__(NT, 1)
momentum_lstm_kernel(const float* __restrict__ x,
                     const float* __restrict__ Wih1, const float* __restrict__ Whh1,
                     const float* __restrict__ bih1, const float* __restrict__ bhh1,
                     const float* __restrict__ Wih2, const float* __restrict__ Whh2,
                     const float* __restrict__ bih2, const float* __restrict__ bhh2,
                     const float* __restrict__ Wd,  const float* __restrict__ bd,
                     const float* __restrict__ Wo,  const float* __restrict__ bo,
                     float* __restrict__ out)
{
    extern __shared__ float sm[];
    float* sW1T = sm + OFF_W1T;
    float* sW2T = sm + OFF_W2T;
    float* sB1  = sm + OFF_B1;
    float* sB2  = sm + OFF_B2;

    const int tid  = threadIdx.x;
    const int lane = tid & 31;
    const int wid  = tid >> 5;

    float* sH1w = sm + OFF_H1 + wid * (H1 * HSTR);
    float* sH2w = sm + OFF_H2 + wid * (H2 * HSTR);
    float* sXd  = sm + OFF_X  + wid * (DD * HSTR);

    // ---------------- staging: transpose + pre-scale i/f/o rows by 0.5 ----------------
    for (int i = tid; i < DD * G1; i += NT) {
        int d = i >> 8, g = i & 255;
        float s = ((g >> 6) == 2) ? 1.0f : 0.5f;       // gate order i,f,g,o
        sW1T[d * G1 + g] = s * Wih1[g * DD + d];
    }
    for (int i = tid; i < H1 * G1; i += NT) {
        int k = i >> 8, g = i & 255;
        float s = ((g >> 6) == 2) ? 1.0f : 0.5f;
        sW1T[(DD + k) * G1 + g] = s * Whh1[g * H1 + k];
    }
    for (int i = tid; i < (H1 + H2) * G2; i += NT) {
        int k = i >> 7, g = i & 127;
        float s = ((g >> 5) == 2) ? 1.0f : 0.5f;
        sW2T[i] = s * ((k < H1) ? Wih2[g * H1 + k] : Whh2[g * H2 + (k - H1)]);
    }
    if (tid < G1) {
        float s = ((tid >> 6) == 2) ? 1.0f : 0.5f;
        sB1[tid] = s * (bih1[tid] + bhh1[tid]);
    }
    if (tid < G2) {
        float s = ((tid >> 5) == 2) ? 1.0f : 0.5f;
        sB2[tid] = s * (bih2[tid] + bhh2[tid]);
    }
    __syncthreads();

    // ---------------- warp-local tilings ----------------
    const int u01 = 2 * lane;               // layer1: lanes span 64 units
    const int u02 = 2 * (lane & 15);        // layer2: 16 lanes span 32 units
    const int bh2 = (lane >> 4) * 4;        // layer2: half-warp batch split (4 each)

    // natural unit-pair biases (zero MOVs)
    const u64t bia1_0 = lds64(&sB1[0 * H1 + u01]);
    const u64t bia1_1 = lds64(&sB1[1 * H1 + u01]);
    const u64t bia1_2 = lds64(&sB1[2 * H1 + u01]);
    const u64t bia1_3 = lds64(&sB1[3 * H1 + u01]);
    const u64t bia2_0 = lds64(&sB2[0 * H2 + u02]);
    const u64t bia2_1 = lds64(&sB2[1 * H2 + u02]);
    const u64t bia2_2 = lds64(&sB2[2 * H2 + u02]);
    const u64t bia2_3 = lds64(&sB2[3 * H2 + u02]);

    const int gw = wid * GRID + blockIdx.x;

    for (int tau = gw; tau < NTASKS; tau += WSLOTS) {
        const float* xg = x + (size_t)tau * TB * (TT * DD);

        for (int i = lane; i < H1 * HSTR; i += 32) sH1w[i] = 0.0f;
        for (int i = lane; i < H2 * HSTR; i += 32) sH2w[i] = 0.0f;
        __syncwarp();

        // cell state: c[u][b], u = u01+u
        float c1a[TB], c1b[TB];
        #pragma unroll
        for (int b = 0; b < TB; b++) { c1a[b] = 0.0f; c1b[b] = 0.0f; }
        float c2a[4], c2b[4];
        #pragma unroll
        for (int b = 0; b < 4; b++) { c2a[b] = 0.0f; c2b[b] = 0.0f; }

        // prefetch x(t=0): 56 values
        float xr[2];
        #pragma unroll
        for (int j = 0; j < 2; j++) {
            int idx = 32 * j + lane;
            if (idx < DD * TB) {
                int b = idx / DD, d = idx - b * DD;
                xr[j] = xg[b * (TT * DD) + d];
            }
        }

        for (int t = 0; t < TT; t++) {
            // store x(t) duplicated; prefetch x(t+1)
            #pragma unroll
            for (int j = 0; j < 2; j++) {
                int idx = 32 * j + lane;
                if (idx < DD * TB) {
                    int b = idx / DD, d = idx - b * DD;
                    sts64(&sXd[d * HSTR + 2 * b], pk2(xr[j], xr[j]));
                }
            }
            __syncwarp();
            if (t + 1 < TT) {
                #pragma unroll
                for (int j = 0; j < 2; j++) {
                    int idx = 32 * j + lane;
                    if (idx < DD * TB) {
                        int b = idx / DD, d = idx - b * DD;
                        xr[j] = xg[b * (TT * DD) + (t + 1) * DD + d];
                    }
                }
            }

            // ============ layer 1 gates: acc[g][b] = (gate_u0, gate_u1) ============
            u64t a0[TB], a1g[TB], a2g[TB], a3[TB];
            #pragma unroll
            for (int b = 0; b < TB; b++) {
                a0[b] = bia1_0; a1g[b] = bia1_1; a2g[b] = bia1_2; a3[b] = bia1_3;
            }
            #pragma unroll
            for (int d = 0; d < DD; d++) {
                u64t w0 = lds64(&sW1T[d * G1 + 0 * H1 + u01]);
                u64t w1 = lds64(&sW1T[d * G1 + 1 * H1 + u01]);
                u64t w2 = lds64(&sW1T[d * G1 + 2 * H1 + u01]);
                u64t w3 = lds64(&sW1T[d * G1 + 3 * H1 + u01]);
                #pragma unroll
                for (int p = 0; p < 4; p++) {
                    ulonglong2 xq = lds128(&sXd[d * HSTR + 4 * p]);
                    a0[2*p]   = fma2(w0, xq.x, a0[2*p]);   a0[2*p+1]  = fma2(w0, xq.y, a0[2*p+1]);
                    a1g[2*p]  = fma2(w1, xq.x, a1g[2*p]);  a1g[2*p+1] = fma2(w1, xq.y, a1g[2*p+1]);
                    a2g[2*p]  = fma2(w2, xq.x, a2g[2*p]);  a2g[2*p+1] = fma2(w2, xq.y, a2g[2*p+1]);
                    a3[2*p]   = fma2(w3, xq.x, a3[2*p]);   a3[2*p+1]  = fma2(w3, xq.y, a3[2*p+1]);
                }
            }
            #pragma unroll 2
            for (int k = 0; k < H1; k++) {
                u64t w0 = lds64(&sW1T[(DD + k) * G1 + 0 * H1 + u01]);
                u64t w1 = lds64(&sW1T[(DD + k) * G1 + 1 * H1 + u01]);
                u64t w2 = lds64(&sW1T[(DD + k) * G1 + 2 * H1 + u01]);
                u64t w3 = lds64(&sW1T[(DD + k) * G1 + 3 * H1 + u01]);
                #pragma unroll
                for (int p = 0; p < 4; p++) {
                    ulonglong2 hq = lds128(&sH1w[k * HSTR + 4 * p]);
                    a0[2*p]   = fma2(w0, hq.x, a0[2*p]);   a0[2*p+1]  = fma2(w0, hq.y, a0[2*p+1]);
                    a1g[2*p]  = fma2(w1, hq.x, a1g[2*p]);  a1g[2*p+1] = fma2(w1, hq.y, a1g[2*p+1]);
                    a2g[2*p]  = fma2(w2, hq.x, a2g[2*p]);  a2g[2*p+1] = fma2(w2, hq.y, a2g[2*p+1]);
                    a3[2*p]   = fma2(w3, hq.x, a3[2*p]);   a3[2*p+1]  = fma2(w3, hq.y, a3[2*p+1]);
                }
            }
            __syncwarp();                      // WAR on old h1

            // pointwise layer1: per batch, units (u01, u01+1) in (lo,hi)
            float h0[TB], h1v[TB];
            #pragma unroll
            for (int b = 0; b < TB; b++) {
                float i0, i1, f0, f1, g0, g1, o0, o1;
                upk(a0[b],  i0, i1);
                upk(a1g[b], f0, f1);
                upk(a2g[b], g0, g1);
                upk(a3[b],  o0, o1);
                float cc0 = sig_h(f0) * c1a[b] + sig_h(i0) * tanha(g0);
                float cc1 = sig_h(f1) * c1b[b] + sig_h(i1) * tanha(g1);
                c1a[b] = cc0; c1b[b] = cc1;
                h0[b]  = sig_h(o0) * tanha(cc0);
                h1v[b] = sig_h(o1) * tanha(cc1);
            }
            #pragma unroll
            for (int p = 0; p < 4; p++) {
                ulonglong2 q0, q1;
                q0.x = pk2(h0[2*p], h0[2*p]);     q0.y = pk2(h0[2*p+1], h0[2*p+1]);
                q1.x = pk2(h1v[2*p], h1v[2*p]);   q1.y = pk2(h1v[2*p+1], h1v[2*p+1]);
                sts128(&sH1w[(u01 + 0) * HSTR + 4 * p], q0);
                sts128(&sH1w[(u01 + 1) * HSTR + 4 * p], q1);
            }
            __syncwarp();                      // RAW: new h1 visible

            // ============ layer 2 gates: acc[g][b] = (gate_u0, gate_u1) ============
            u64t b0[4], b1g[4], b2g[4], b3[4];
            #pragma unroll
            for (int b = 0; b < 4; b++) {
                b0[b] = bia2_0; b1g[b] = bia2_1; b2g[b] = bia2_2; b3[b] = bia2_3;
            }
            #pragma unroll 2
            for (int k = 0; k < H1; k++) {     // input = new h1
                u64t w0 = lds64(&sW2T[k * G2 + 0 * H2 + u02]);
                u64t w1 = lds64(&sW2T[k * G2 + 1 * H2 + u02]);
                u64t w2 = lds64(&sW2T[k * G2 + 2 * H2 + u02]);
                u64t w3 = lds64(&sW2T[k * G2 + 3 * H2 + u02]);
                #pragma unroll
                for (int p = 0; p < 2; p++) {
                    ulonglong2 hq = lds128(&sH1w[k * HSTR + 2 * bh2 + 4 * p]);
                    b0[2*p]  = fma2(w0, hq.x, b0[2*p]);   b0[2*p+1]  = fma2(w0, hq.y, b0[2*p+1]);
                    b1g[2*p] = fma2(w1, hq.x, b1g[2*p]);  b1g[2*p+1] = fma2(w1, hq.y, b1g[2*p+1]);
                    b2g[2*p] = fma2(w2, hq.x, b2g[2*p]);  b2g[2*p+1] = fma2(w2, hq.y, b2g[2*p+1]);
                    b3[2*p]  = fma2(w3, hq.x, b3[2*p]);   b3[2*p+1]  = fma2(w3, hq.y, b3[2*p+1]);
                }
            }
            #pragma unroll 2
            for (int k = 0; k < H2; k++) {     // recurrent = old h2
                u64t w0 = lds64(&sW2T[(H1 + k) * G2 + 0 * H2 + u02]);
                u64t w1 = lds64(&sW2T[(H1 + k) * G2 + 1 * H2 + u02]);
                u64t w2 = lds64(&sW2T[(H1 + k) * G2 + 2 * H2 + u02]);
                u64t w3 = lds64(&sW2T[(H1 + k) * G2 + 3 * H2 + u02]);
                #pragma unroll
                for (int p = 0; p < 2; p++) {
                    ulonglong2 hq = lds128(&sH2w[k * HSTR + 2 * bh2 + 4 * p]);
                    b0[2*p]  = fma2(w0, hq.x, b0[2*p]);   b0[2*p+1]  = fma2(w0, hq.y, b0[2*p+1]);
                    b1g[2*p] = fma2(w1, hq.x, b1g[2*p]);  b1g[2*p+1] = fma2(w1, hq.y, b1g[2*p+1]);
                    b2g[2*p] = fma2(w2, hq.x, b2g[2*p]);  b2g[2*p+1] = fma2(w2, hq.y, b2g[2*p+1]);
                    b3[2*p]  = fma2(w3, hq.x, b3[2*p]);   b3[2*p+1]  = fma2(w3, hq.y, b3[2*p+1]);
                }
            }
            __syncwarp();                      // WAR on old h2

            // pointwise layer2
            float g0s[4], g1s[4];
            #pragma unroll
            for (int b = 0; b < 4; b++) {
                float i0, i1, f0, f1, g0, g1, o0, o1;
                upk(b0[b],  i0, i1);
                upk(b1g[b], f0, f1);
                upk(b2g[b], g0, g1);
                upk(b3[b],  o0, o1);
                float cc0 = sig_h(f0) * c2a[b] + sig_h(i0) * tanha(g0);
                float cc1 = sig_h(f1) * c2b[b] + sig_h(i1) * tanha(g1);
                c2a[b] = cc0; c2b[b] = cc1;
                g0s[b] = sig_h(o0) * tanha(cc0);
                g1s[b] = sig_h(o1) * tanha(cc1);
            }
            #pragma unroll
            for (int p = 0; p < 2; p++) {
                ulonglong2 q0, q1;
                q0.x = pk2(g0s[2*p], g0s[2*p]);   q0.y = pk2(g0s[2*p+1], g0s[2*p+1]);
                q1.x = pk2(g1s[2*p], g1s[2*p]);   q1.y = pk2(g1s[2*p+1], g1s[2*p+1]);
                sts128(&sH2w[(u02 + 0) * HSTR + 2 * bh2 + 4 * p], q0);
                sts128(&sH2w[(u02 + 1) * HSTR + 2 * bh2 + 4 * p], q1);
            }
            __syncwarp();                      // new h2 visible
        }

        // ================= head: dense(16)+relu -> dot(16)+sigmoid =============
        if (lane < TB) {
            const int b = lane;
            float hv[H2];
            #pragma unroll
            for (int k = 0; k < H2; k++) hv[k] = sH2w[k * HSTR + 2 * b];
            float o = __ldg(&bo[0]);
            #pragma unroll
            for (int j = 0; j < 16; j++) {
                float s = __ldg(&bd[j]);
                #pragma unroll
                for (int k = 0; k < H2; k++) s += hv[k] * __ldg(&Wd[j * H2 + k]);
                o += fmaxf(s, 0.0f) * __ldg(&Wo[j]);
            }
            out[tau * TB + b] = sigx(o);
        }
        __syncwarp();
    }
}

extern "C" void kernel_launch(void* const* d_in, const int* in_sizes, int n_in,
                              void* d_out, int out_size) {
    const float* x    = (const float*)d_in[0];
    const float* Wih1 = (const float*)d_in[1];
    const float* Whh1 = (const float*)d_in[2];
    const float* bih1 = (const float*)d_in[3];
    const float* bhh1 = (const float*)d_in[4];
    const float* Wih2 = (const float*)d_in[5];
    const float* Whh2 = (const float*)d_in[6];
    const float* bih2 = (const float*)d_in[7];
    const float* bhh2 = (const float*)d_in[8];
    const float* Wd   = (const float*)d_in[9];
    const float* bd   = (const float*)d_in[10];
    const float* Wo   = (const float*)d_in[11];
    const float* bo   = (const float*)d_in[12];
    float* out = (float*)d_out;

    static bool attr_set = false;
    if (!attr_set) {
        cudaFuncSetAttribute(momentum_lstm_kernel,
                             cudaFuncAttributeMaxDynamicSharedMemorySize, SMEM_BYTES);
        attr_set = true;
    }

    momentum_lstm_kernel<<<GRID, NT, SMEM_BYTES>>>(
        x, Wih1, Whh1, bih1, bhh1, Wih2, Whh2, bih2, bhh2, Wd, bd, Wo, bo, out);
}

// round 10
// speedup vs baseline: 1.0098x; 1.0098x over previous
#include <cuda_runtime.h>
#include <cuda_bf16.h>

// MomentumLSTM v9: v6 base (best: 2302us) + LDS.128 everywhere it is free:
//  - weights stored INTERLEAVED per unit-pair: [i0,i1,f0,f1,g0,g1,o0,o1] -> 2 LDS.128/k
//  - h/x batch pairs read 2-at-a-time via LDS.128 (stride 12, 16B-aligned rows)
// Same unique bytes, same wavefronts, ~7% fewer issue slots. Math identical to v6.

#define BATCH  32768
#define TT     60
#define DD     7
#define H1     64
#define G1     256
#define H2     32
#define G2     128
#define NT     384
#define GRID   152
#define TB     8                 // batches per warp-task
#define NTASKS (BATCH / TB)      // 4096
#define WSLOTS (GRID * 12)       // 1824
#define HS1    12                // [64][12] per-warp h1 slab (16B-aligned rows)
#define HS2    12                // [32][12]
#define XS     8                 // [7][8]

// SMEM float offsets
#define OFF_W1T 0                // [71][256] interleaved (i/f/o pre-scaled 0.5)
#define OFF_W2T 18176            // [96][128] interleaved
#define OFF_B1  30464            // [256]
#define OFF_B2  30720            // [128]
#define OFF_H1  30848            // 12 x 768
#define OFF_H2  40064            // 12 x 384
#define OFF_X   44672            // 12 x 64
#define SMEM_FLOATS 45440
#define SMEM_BYTES  (SMEM_FLOATS * 4)   // 181760

typedef unsigned long long u64t;

__device__ __forceinline__ u64t pk2(float a, float b) {
    u64t r; asm("mov.b64 %0, {%1, %2};" : "=l"(r) : "f"(a), "f"(b)); return r;
}
__device__ __forceinline__ void upk(u64t v, float& lo, float& hi) {
    asm("mov.b64 {%0, %1}, %2;" : "=f"(lo), "=f"(hi) : "l"(v));
}
__device__ __forceinline__ u64t fma2(u64t a, u64t b, u64t c) {
    u64t d; asm("fma.rn.f32x2 %0, %1, %2, %3;" : "=l"(d) : "l"(a), "l"(b), "l"(c)); return d;
}
__device__ __forceinline__ u64t lds64(const float* p) {
    return *reinterpret_cast<const u64t*>(p);
}
__device__ __forceinline__ void sts64(float* p, u64t v) {
    *reinterpret_cast<u64t*>(p) = v;
}
__device__ __forceinline__ ulonglong2 lds128(const float* p) {
    return *reinterpret_cast<const ulonglong2*>(p);
}
__device__ __forceinline__ float tanha(float x) {
    float y; asm("tanh.approx.f32 %0, %1;" : "=f"(y) : "f"(x)); return y;
}
// acc already holds x/2 (weights pre-scaled): sigmoid(x) = 0.5*tanh(x/2)+0.5
__device__ __forceinline__ float sig_h(float halfx) {
    return fmaf(0.5f, tanha(halfx), 0.5f);
}
__device__ __forceinline__ float sigx(float x) {   // exact, output only
    return __fdividef(1.0f, 1.0f + __expf(-x));
}

__global__ void __launch_bounds__(NT, 1)
momentum_lstm_kernel(const float* __restrict__ x,
                     const float* __restrict__ Wih1, const float* __restrict__ Whh1,
                     const float* __restrict__ bih1, const float* __restrict__ bhh1,
                     const float* __restrict__ Wih2, const float* __restrict__ Whh2,
                     const float* __restrict__ bih2, const float* __restrict__ bhh2,
                     const float* __restrict__ Wd,  const float* __restrict__ bd,
                     const float* __restrict__ Wo,  const float* __restrict__ bo,
                     float* __restrict__ out)
{
    extern __shared__ float sm[];
    float* sW1T = sm + OFF_W1T;
    float* sW2T = sm + OFF_W2T;
    float* sB1  = sm + OFF_B1;
    float* sB2  = sm + OFF_B2;

    const int tid  = threadIdx.x;
    const int lane = tid & 31;
    const int wid  = tid >> 5;

    float* sH1w = sm + OFF_H1 + wid * (H1 * HS1);
    float* sH2w = sm + OFF_H2 + wid * (H2 * HS2);
    float* sXw  = sm + OFF_X  + wid * 64;

    // ------- staging: interleaved layout [row][pair j][i0,i1,f0,f1,g0,g1,o0,o1] -------
    // i/f/o rows pre-scaled by 0.5 (gate order i,f,g,o)
    for (int i = tid; i < (DD + H1) * G1; i += NT) {
        int r = i >> 8, off = i & 255;
        int j = off >> 3, g = (off >> 1) & 3, s = off & 1;
        int unit = 2 * j + s;
        int grow = g * H1 + unit;
        float v = (r < DD) ? Wih1[grow * DD + r] : Whh1[grow * H1 + (r - DD)];
        sW1T[i] = ((g == 2) ? 1.0f : 0.5f) * v;
    }
    for (int i = tid; i < (H1 + H2) * G2; i += NT) {
        int k = i >> 7, off = i & 127;
        int j = off >> 3, g = (off >> 1) & 3, s = off & 1;
        int unit = 2 * j + s;
        int grow = g * H2 + unit;
        float v = (k < H1) ? Wih2[grow * H1 + k] : Whh2[grow * H2 + (k - H1)];
        sW2T[i] = ((g == 2) ? 1.0f : 0.5f) * v;
    }
    if (tid < G1) {
        float s = ((tid >> 6) == 2) ? 1.0f : 0.5f;
        sB1[tid] = s * (bih1[tid] + bhh1[tid]);
    }
    if (tid < G2) {
        float s = ((tid >> 5) == 2) ? 1.0f : 0.5f;
        sB2[tid] = s * (bih2[tid] + bhh2[tid]);
    }
    __syncthreads();

    // ---------------- warp-local tilings ----------------
    const int u01 = 2 * lane;               // layer1: lanes span 64 units
    const int u02 = 2 * (lane & 15);        // layer2: 16 lanes span 32 units
    const int bh2 = (lane >> 4) * 4;        // layer2: half-warp batch split (4 each)

    // natural bias pairs (b_u0,b_u1): unpack once, duplicate per step as in v6
    const u64t bia1_0 = lds64(&sB1[0 * H1 + u01]);
    const u64t bia1_1 = lds64(&sB1[1 * H1 + u01]);
    const u64t bia1_2 = lds64(&sB1[2 * H1 + u01]);
    const u64t bia1_3 = lds64(&sB1[3 * H1 + u01]);
    const u64t bia2_0 = lds64(&sB2[0 * H2 + u02]);
    const u64t bia2_1 = lds64(&sB2[1 * H2 + u02]);
    const u64t bia2_2 = lds64(&sB2[2 * H2 + u02]);
    const u64t bia2_3 = lds64(&sB2[3 * H2 + u02]);

    const int gw = wid * GRID + blockIdx.x;

    for (int tau = gw; tau < NTASKS; tau += WSLOTS) {
        const float* xg = x + (size_t)tau * TB * (TT * DD);

        for (int i = lane; i < H1 * HS1; i += 32) sH1w[i] = 0.0f;
        for (int i = lane; i < H2 * HS2; i += 32) sH2w[i] = 0.0f;
        __syncwarp();

        float c1[2][TB];
        #pragma unroll
        for (int u = 0; u < 2; u++)
            #pragma unroll
            for (int b = 0; b < TB; b++) c1[u][b] = 0.0f;
        float c2[2][4];
        #pragma unroll
        for (int u = 0; u < 2; u++)
            #pragma unroll
            for (int b = 0; b < 4; b++) c2[u][b] = 0.0f;

        // prefetch x(t=0)
        float xr[2];
        #pragma unroll
        for (int j = 0; j < 2; j++) {
            int idx = 32 * j + lane;
            if (idx < DD * TB) {
                int b = idx / DD, d = idx - b * DD;
                xr[j] = xg[b * (TT * DD) + d];
            }
        }

        for (int t = 0; t < TT; t++) {
            #pragma unroll
            for (int j = 0; j < 2; j++) {
                int idx = 32 * j + lane;
                if (idx < DD * TB) {
                    int b = idx / DD, d = idx - b * DD;
                    sXw[d * XS + b] = xr[j];
                }
            }
            __syncwarp();
            if (t + 1 < TT) {
                #pragma unroll
                for (int j = 0; j < 2; j++) {
                    int idx = 32 * j + lane;
                    if (idx < DD * TB) {
                        int b = idx / DD, d = idx - b * DD;
                        xr[j] = xg[b * (TT * DD) + (t + 1) * DD + d];
                    }
                }
            }

            // ================= layer 1 gates =================
            u64t a1[2][4][4];
            #pragma unroll
            for (int g = 0; g < 4; g++) {
                float blo, bhi;
                upk(g == 0 ? bia1_0 : g == 1 ? bia1_1 : g == 2 ? bia1_2 : bia1_3, blo, bhi);
                u64t plo = pk2(blo, blo), phi = pk2(bhi, bhi);
                #pragma unroll
                for (int p = 0; p < 4; p++) { a1[0][g][p] = plo; a1[1][g][p] = phi; }
            }
            #pragma unroll
            for (int d = 0; d < DD; d++) {
                const float* wr = &sW1T[d * G1 + lane * 8];
                ulonglong2 wq0 = lds128(wr);        // (i0,i1),(f0,f1)
                ulonglong2 wq1 = lds128(wr + 4);    // (g0,g1),(o0,o1)
                float wi0, wi1, wf0, wf1, wg0, wg1, wo0, wo1;
                upk(wq0.x, wi0, wi1); upk(wq0.y, wf0, wf1);
                upk(wq1.x, wg0, wg1); upk(wq1.y, wo0, wo1);
                u64t w00 = pk2(wi0, wi0), w01 = pk2(wi1, wi1);
                u64t w10 = pk2(wf0, wf0), w11 = pk2(wf1, wf1);
                u64t w20 = pk2(wg0, wg0), w21 = pk2(wg1, wg1);
                u64t w30 = pk2(wo0, wo0), w31 = pk2(wo1, wo1);
                #pragma unroll
                for (int pp = 0; pp < 2; pp++) {
                    ulonglong2 xq = lds128(&sXw[d * XS + 4 * pp]);   // pairs 2pp, 2pp+1
                    a1[0][0][2*pp]   = fma2(w00, xq.x, a1[0][0][2*pp]);
                    a1[0][0][2*pp+1] = fma2(w00, xq.y, a1[0][0][2*pp+1]);
                    a1[1][0][2*pp]   = fma2(w01, xq.x, a1[1][0][2*pp]);
                    a1[1][0][2*pp+1] = fma2(w01, xq.y, a1[1][0][2*pp+1]);
                    a1[0][1][2*pp]   = fma2(w10, xq.x, a1[0][1][2*pp]);
                    a1[0][1][2*pp+1] = fma2(w10, xq.y, a1[0][1][2*pp+1]);
                    a1[1][1][2*pp]   = fma2(w11, xq.x, a1[1][1][2*pp]);
                    a1[1][1][2*pp+1] = fma2(w11, xq.y, a1[1][1][2*pp+1]);
                    a1[0][2][2*pp]   = fma2(w20, xq.x, a1[0][2][2*pp]);
                    a1[0][2][2*pp+1] = fma2(w20, xq.y, a1[0][2][2*pp+1]);
                    a1[1][2][2*pp]   = fma2(w21, xq.x, a1[1][2][2*pp]);
                    a1[1][2][2*pp+1] = fma2(w21, xq.y, a1[1][2][2*pp+1]);
                    a1[0][3][2*pp]   = fma2(w30, xq.x, a1[0][3][2*pp]);
                    a1[0][3][2*pp+1] = fma2(w30, xq.y, a1[0][3][2*pp+1]);
                    a1[1][3][2*pp]   = fma2(w31, xq.x, a1[1][3][2*pp]);
                    a1[1][3][2*pp+1] = fma2(w31, xq.y, a1[1][3][2*pp+1]);
                }
            }
            #pragma unroll 2
            for (int k = 0; k < H1; k++) {
                const float* wr = &sW1T[(DD + k) * G1 + lane * 8];
                ulonglong2 wq0 = lds128(wr);
                ulonglong2 wq1 = lds128(wr + 4);
                float wi0, wi1, wf0, wf1, wg0, wg1, wo0, wo1;
                upk(wq0.x, wi0, wi1); upk(wq0.y, wf0, wf1);
                upk(wq1.x, wg0, wg1); upk(wq1.y, wo0, wo1);
                u64t w00 = pk2(wi0, wi0), w01 = pk2(wi1, wi1);
                u64t w10 = pk2(wf0, wf0), w11 = pk2(wf1, wf1);
                u64t w20 = pk2(wg0, wg0), w21 = pk2(wg1, wg1);
                u64t w30 = pk2(wo0, wo0), w31 = pk2(wo1, wo1);
                #pragma unroll
                for (int pp = 0; pp < 2; pp++) {
                    ulonglong2 hq = lds128(&sH1w[k * HS1 + 4 * pp]);
                    a1[0][0][2*pp]   = fma2(w00, hq.x, a1[0][0][2*pp]);
                    a1[0][0][2*pp+1] = fma2(w00, hq.y, a1[0][0][2*pp+1]);
                    a1[1][0][2*pp]   = fma2(w01, hq.x, a1[1][0][2*pp]);
                    a1[1][0][2*pp+1] = fma2(w01, hq.y, a1[1][0][2*pp+1]);
                    a1[0][1][2*pp]   = fma2(w10, hq.x, a1[0][1][2*pp]);
                    a1[0][1][2*pp+1] = fma2(w10, hq.y, a1[0][1][2*pp+1]);
                    a1[1][1][2*pp]   = fma2(w11, hq.x, a1[1][1][2*pp]);
                    a1[1][1][2*pp+1] = fma2(w11, hq.y, a1[1][1][2*pp+1]);
                    a1[0][2][2*pp]   = fma2(w20, hq.x, a1[0][2][2*pp]);
                    a1[0][2][2*pp+1] = fma2(w20, hq.y, a1[0][2][2*pp+1]);
                    a1[1][2][2*pp]   = fma2(w21, hq.x, a1[1][2][2*pp]);
                    a1[1][2][2*pp+1] = fma2(w21, hq.y, a1[1][2][2*pp+1]);
                    a1[0][3][2*pp]   = fma2(w30, hq.x, a1[0][3][2*pp]);
                    a1[0][3][2*pp+1] = fma2(w30, hq.y, a1[0][3][2*pp+1]);
                    a1[1][3][2*pp]   = fma2(w31, hq.x, a1[1][3][2*pp]);
                    a1[1][3][2*pp+1] = fma2(w31, hq.y, a1[1][3][2*pp+1]);
                }
            }
            __syncwarp();                      // WAR on old h1

            // pointwise layer1 + write new h1
            #pragma unroll
            for (int u = 0; u < 2; u++) {
                #pragma unroll
                for (int p = 0; p < 4; p++) {
                    float gi[2], gf[2], gg[2], go[2], hh[2];
                    upk(a1[u][0][p], gi[0], gi[1]);
                    upk(a1[u][1][p], gf[0], gf[1]);
                    upk(a1[u][2][p], gg[0], gg[1]);
                    upk(a1[u][3][p], go[0], go[1]);
                    #pragma unroll
                    for (int s = 0; s < 2; s++) {
                        float ii = sig_h(gi[s]);
                        float ff = sig_h(gf[s]);
                        float g_ = tanha(gg[s]);
                        float oo = sig_h(go[s]);
                        float cc = ff * c1[u][2 * p + s] + ii * g_;
                        c1[u][2 * p + s] = cc;
                        hh[s] = oo * tanha(cc);
                    }
                    sts64(&sH1w[(u01 + u) * HS1 + 2 * p], pk2(hh[0], hh[1]));
                }
            }
            __syncwarp();                      // RAW: new h1 visible

            // ================= layer 2 gates =================
            u64t a2[2][4][2];
            #pragma unroll
            for (int g = 0; g < 4; g++) {
                float blo, bhi;
                upk(g == 0 ? bia2_0 : g == 1 ? bia2_1 : g == 2 ? bia2_2 : bia2_3, blo, bhi);
                u64t plo = pk2(blo, blo), phi = pk2(bhi, bhi);
                #pragma unroll
                for (int p = 0; p < 2; p++) { a2[0][g][p] = plo; a2[1][g][p] = phi; }
            }
            #pragma unroll 2
            for (int k = 0; k < H1; k++) {     // input = new h1
                const float* wr = &sW2T[k * G2 + (lane & 15) * 8];
                ulonglong2 wq0 = lds128(wr);
                ulonglong2 wq1 = lds128(wr + 4);
                float wi0, wi1, wf0, wf1, wg0, wg1, wo0, wo1;
                upk(wq0.x, wi0, wi1); upk(wq0.y, wf0, wf1);
                upk(wq1.x, wg0, wg1); upk(wq1.y, wo0, wo1);
                u64t w00 = pk2(wi0, wi0), w01 = pk2(wi1, wi1);
                u64t w10 = pk2(wf0, wf0), w11 = pk2(wf1, wf1);
                u64t w20 = pk2(wg0, wg0), w21 = pk2(wg1, wg1);
                u64t w30 = pk2(wo0, wo0), w31 = pk2(wo1, wo1);
                ulonglong2 hq = lds128(&sH1w[k * HS1 + bh2]);   // pairs 0,1 of half-warp
                a2[0][0][0] = fma2(w00, hq.x, a2[0][0][0]);
                a2[0][0][1] = fma2(w00, hq.y, a2[0][0][1]);
                a2[1][0][0] = fma2(w01, hq.x, a2[1][0][0]);
                a2[1][0][1] = fma2(w01, hq.y, a2[1][0][1]);
                a2[0][1][0] = fma2(w10, hq.x, a2[0][1][0]);
                a2[0][1][1] = fma2(w10, hq.y, a2[0][1][1]);
                a2[1][1][0] = fma2(w11, hq.x, a2[1][1][0]);
                a2[1][1][1] = fma2(w11, hq.y, a2[1][1][1]);
                a2[0][2][0] = fma2(w20, hq.x, a2[0][2][0]);
                a2[0][2][1] = fma2(w20, hq.y, a2[0][2][1]);
                a2[1][2][0] = fma2(w21, hq.x, a2[1][2][0]);
                a2[1][2][1] = fma2(w21, hq.y, a2[1][2][1]);
                a2[0][3][0] = fma2(w30, hq.x, a2[0][3][0]);
                a2[0][3][1] = fma2(w30, hq.y, a2[0][3][1]);
                a2[1][3][0] = fma2(w31, hq.x, a2[1][3][0]);
                a2[1][3][1] = fma2(w31, hq.y, a2[1][3][1]);
            }
            #pragma unroll 2
            for (int k = 0; k < H2; k++) {     // recurrent = old h2
                const float* wr = &sW2T[(H1 + k) * G2 + (lane & 15) * 8];
                ulonglong2 wq0 = lds128(wr);
                ulonglong2 wq1 = lds128(wr + 4);
                float wi0, wi1, wf0, wf1, wg0, wg1, wo0, wo1;
                upk(wq0.x, wi0, wi1); upk(wq0.y, wf0, wf1);
                upk(wq1.x, wg0, wg1); upk(wq1.y, wo0, wo1);
                u64t w00 = pk2(wi0, wi0), w01 = pk2(wi1, wi1);
                u64t w10 = pk2(wf0, wf0), w11 = pk2(wf1, wf1);
                u64t w20 = pk2(wg0, wg0), w21 = pk2(wg1, wg1);
                u64t w30 = pk2(wo0, wo0), w31 = pk2(wo1, wo1);
                ulonglong2 hq = lds128(&sH2w[k * HS2 + bh2]);
                a2[0][0][0] = fma2(w00, hq.x, a2[0][0][0]);
                a2[0][0][1] = fma2(w00, hq.y, a2[0][0][1]);
                a2[1][0][0] = fma2(w01, hq.x, a2[1][0][0]);
                a2[1][0][1] = fma2(w01, hq.y, a2[1][0][1]);
                a2[0][1][0] = fma2(w10, hq.x, a2[0][1][0]);
                a2[0][1][1] = fma2(w10, hq.y, a2[0][1][1]);
                a2[1][1][0] = fma2(w11, hq.x, a2[1][1][0]);
                a2[1][1][1] = fma2(w11, hq.y, a2[1][1][1]);
                a2[0][2][0] = fma2(w20, hq.x, a2[0][2][0]);
                a2[0][2][1] = fma2(w20, hq.y, a2[0][2][1]);
                a2[1][2][0] = fma2(w21, hq.x, a2[1][2][0]);
                a2[1][2][1] = fma2(w21, hq.y, a2[1][2][1]);
                a2[0][3][0] = fma2(w30, hq.x, a2[0][3][0]);
                a2[0][3][1] = fma2(w30, hq.y, a2[0][3][1]);
                a2[1][3][0] = fma2(w31, hq.x, a2[1][3][0]);
                a2[1][3][1] = fma2(w31, hq.y, a2[1][3][1]);
            }
            __syncwarp();                      // WAR on old h2

            // pointwise layer2 + write new h2
            #pragma unroll
            for (int u = 0; u < 2; u++) {
                #pragma unroll
                for (int p = 0; p < 2; p++) {
                    float gi[2], gf[2], gg[2], go[2], hh[2];
                    upk(a2[u][0][p], gi[0], gi[1]);
                    upk(a2[u][1][p], gf[0], gf[1]);
                    upk(a2[u][2][p], gg[0], gg[1]);
                    upk(a2[u][3][p], go[0], go[1]);
                    #pragma unroll
                    for (int s = 0; s < 2; s++) {
                        float ii = sig_h(gi[s]);
                        float ff = sig_h(gf[s]);
                        float g_ = tanha(gg[s]);
                        float oo = sig_h(go[s]);
                        float cc = ff * c2[u][2 * p + s] + ii * g_;
                        c2[u][2 * p + s] = cc;
                        hh[s] = oo * tanha(cc);
                    }
                    sts64(&sH2w[(u02 + u) * HS2 + bh2 + 2 * p], pk2(hh[0], hh[1]));
                }
            }
            __syncwarp();                      // new h2 visible
        }

        // ================= head: dense(16)+relu -> dot(16)+sigmoid =============
        if (lane < TB) {
            const int b = lane;
            float hv[H2];
            #pragma unroll
            for (int k = 0; k < H2; k++) hv[k] = sH2w[k * HS2 + b];
            float o = __ldg(&bo[0]);
            #pragma unroll
            for (int j = 0; j < 16; j++) {
                float s = __ldg(&bd[j]);
                #pragma unroll
                for (int k = 0; k < H2; k++) s += hv[k] * __ldg(&Wd[j * H2 + k]);
                o += fmaxf(s, 0.0f) * __ldg(&Wo[j]);
            }
            out[tau * TB + b] = sigx(o);
        }
        __syncwarp();
    }
}

extern "C" void kernel_launch(void* const* d_in, const int* in_sizes, int n_in,
                              void* d_out, int out_size) {
    const float* x    = (const float*)d_in[0];
    const float* Wih1 = (const float*)d_in[1];
    const float* Whh1 = (const float*)d_in[2];
    const float* bih1 = (const float*)d_in[3];
    const float* bhh1 = (const float*)d_in[4];
    const float* Wih2 = (const float*)d_in[5];
    const float* Whh2 = (const float*)d_in[6];
    const float* bih2 = (const float*)d_in[7];
    const float* bhh2 = (const float*)d_in[8];
    const float* Wd   = (const float*)d_in[9];
    const float* bd   = (const float*)d_in[10];
    const float* Wo   = (const float*)d_in[11];
    const float* bo   = (const float*)d_in[12];
    float* out = (float*)d_out;

    static bool attr_set = false;
    if (!attr_set) {
        cudaFuncSetAttribute(momentum_lstm_kernel,
                             cudaFuncAttributeMaxDynamicSharedMemorySize, SMEM_BYTES);
        attr_set = true;
    }

    momentum_lstm_kernel<<<GRID, NT, SMEM_BYTES>>>(
        x, Wih1, Whh1, bih1, bhh1, Wih2, Whh2, bih2, bhh2, Wd, bd, Wo, bo, out);
}

// round 11
// speedup vs baseline: 1.3589x; 1.3458x over previous
#include <cuda_runtime.h>
#include <cuda_bf16.h>

// MomentumLSTM v10: v6 inner loops UNCHANGED (best operand flow: 2302us),
// occupancy raised to 4 warps/SMSP: 512 threads, 16 warps, regs capped 128
// (biases reloaded from SMEM each step instead of held in registers).

#define BATCH  32768
#define TT     60
#define DD     7
#define H1     64
#define G1     256
#define H2     32
#define G2     128
#define NT     512
#define GRID   152
#define TB     8                 // batches per warp-task
#define NTASKS (BATCH / TB)      // 4096
#define WSLOTS (GRID * 16)       // 2432
#define HS1    10                // even stride: [64][10] per-warp h1 slab
#define HS2    10                // [32][10]
#define XS     8                 // [7][8]

// SMEM float offsets
#define OFF_W1T 0                // [71][256] rows 0..6 x-w, 7..70 h-w (i/f/o pre-scaled 0.5)
#define OFF_W2T 18176            // [96][128]
#define OFF_B1  30464            // [256]
#define OFF_B2  30720            // [128]
#define OFF_H1  30848            // 16 x 640
#define OFF_H2  41088            // 16 x 320
#define OFF_X   46208            // 16 x 64
#define SMEM_FLOATS 47232
#define SMEM_BYTES  (SMEM_FLOATS * 4)   // 188928

typedef unsigned long long u64t;

__device__ __forceinline__ u64t pk2(float a, float b) {
    u64t r; asm("mov.b64 %0, {%1, %2};" : "=l"(r) : "f"(a), "f"(b)); return r;
}
__device__ __forceinline__ void upk(u64t v, float& lo, float& hi) {
    asm("mov.b64 {%0, %1}, %2;" : "=f"(lo), "=f"(hi) : "l"(v));
}
__device__ __forceinline__ u64t fma2(u64t a, u64t b, u64t c) {
    u64t d; asm("fma.rn.f32x2 %0, %1, %2, %3;" : "=l"(d) : "l"(a), "l"(b), "l"(c)); return d;
}
__device__ __forceinline__ u64t lds64(const float* p) {
    return *reinterpret_cast<const u64t*>(p);
}
__device__ __forceinline__ void sts64(float* p, u64t v) {
    *reinterpret_cast<u64t*>(p) = v;
}
__device__ __forceinline__ float tanha(float x) {
    float y; asm("tanh.approx.f32 %0, %1;" : "=f"(y) : "f"(x)); return y;
}
// acc already holds x/2 (weights pre-scaled): sigmoid(x) = 0.5*tanh(x/2)+0.5
__device__ __forceinline__ float sig_h(float halfx) {
    return fmaf(0.5f, tanha(halfx), 0.5f);
}
__device__ __forceinline__ float sigx(float x) {   // exact, output only
    return __fdividef(1.0f, 1.0f + __expf(-x));
}

__global__ void __launch_bounds__(NT, 1)
momentum_lstm_kernel(const float* __restrict__ x,
                     const float* __restrict__ Wih1, const float* __restrict__ Whh1,
                     const float* __restrict__ bih1, const float* __restrict__ bhh1,
                     const float* __restrict__ Wih2, const float* __restrict__ Whh2,
                     const float* __restrict__ bih2, const float* __restrict__ bhh2,
                     const float* __restrict__ Wd,  const float* __restrict__ bd,
                     const float* __restrict__ Wo,  const float* __restrict__ bo,
                     float* __restrict__ out)
{
    extern __shared__ float sm[];
    float* sW1T = sm + OFF_W1T;
    float* sW2T = sm + OFF_W2T;
    float* sB1  = sm + OFF_B1;
    float* sB2  = sm + OFF_B2;

    const int tid  = threadIdx.x;
    const int lane = tid & 31;
    const int wid  = tid >> 5;

    float* sH1w = sm + OFF_H1 + wid * (H1 * HS1);
    float* sH2w = sm + OFF_H2 + wid * (H2 * HS2);
    float* sXw  = sm + OFF_X  + wid * 64;

    // ---------------- staging: transpose + pre-scale i/f/o rows by 0.5 ----------------
    for (int i = tid; i < DD * G1; i += NT) {
        int d = i >> 8, g = i & 255;
        float s = ((g >> 6) == 2) ? 1.0f : 0.5f;       // gate order i,f,g,o
        sW1T[d * G1 + g] = s * Wih1[g * DD + d];
    }
    for (int i = tid; i < H1 * G1; i += NT) {
        int k = i >> 8, g = i & 255;
        float s = ((g >> 6) == 2) ? 1.0f : 0.5f;
        sW1T[(DD + k) * G1 + g] = s * Whh1[g * H1 + k];
    }
    for (int i = tid; i < (H1 + H2) * G2; i += NT) {
        int k = i >> 7, g = i & 127;
        float s = ((g >> 5) == 2) ? 1.0f : 0.5f;
        sW2T[i] = s * ((k < H1) ? Wih2[g * H1 + k] : Whh2[g * H2 + (k - H1)]);
    }
    if (tid < G1) {
        float s = ((tid >> 6) == 2) ? 1.0f : 0.5f;
        sB1[tid] = s * (bih1[tid] + bhh1[tid]);
    }
    if (tid < G2) {
        float s = ((tid >> 5) == 2) ? 1.0f : 0.5f;
        sB2[tid] = s * (bih2[tid] + bhh2[tid]);
    }
    __syncthreads();

    // ---------------- warp-local tilings ----------------
    const int u01 = 2 * lane;               // layer1: lanes span 64 units
    const int u02 = 2 * (lane & 15);        // layer2: 16 lanes span 32 units
    const int bh2 = (lane >> 4) * 4;        // layer2: half-warp batch split (4 each)

    const int gw = wid * GRID + blockIdx.x;   // interleaved task id

    for (int tau = gw; tau < NTASKS; tau += WSLOTS) {
        const float* xg = x + (size_t)tau * TB * (TT * DD);

        for (int i = lane; i < H1 * HS1; i += 32) sH1w[i] = 0.0f;
        for (int i = lane; i < H2 * HS2; i += 32) sH2w[i] = 0.0f;
        __syncwarp();

        float c1[2][TB];
        #pragma unroll
        for (int u = 0; u < 2; u++)
            #pragma unroll
            for (int b = 0; b < TB; b++) c1[u][b] = 0.0f;
        float c2[2][4];
        #pragma unroll
        for (int u = 0; u < 2; u++)
            #pragma unroll
            for (int b = 0; b < 4; b++) c2[u][b] = 0.0f;

        // prefetch x(t=0)
        float xr[2];
        #pragma unroll
        for (int j = 0; j < 2; j++) {
            int idx = 32 * j + lane;
            if (idx < DD * TB) {
                int b = idx / DD, d = idx - b * DD;
                xr[j] = xg[b * (TT * DD) + d];
            }
        }

        for (int t = 0; t < TT; t++) {
            // store x(t); prefetch x(t+1)
            #pragma unroll
            for (int j = 0; j < 2; j++) {
                int idx = 32 * j + lane;
                if (idx < DD * TB) {
                    int b = idx / DD, d = idx - b * DD;
                    sXw[d * XS + b] = xr[j];
                }
            }
            __syncwarp();
            if (t + 1 < TT) {
                #pragma unroll
                for (int j = 0; j < 2; j++) {
                    int idx = 32 * j + lane;
                    if (idx < DD * TB) {
                        int b = idx / DD, d = idx - b * DD;
                        xr[j] = xg[b * (TT * DD) + (t + 1) * DD + d];
                    }
                }
            }

            // ================= layer 1 gates =================
            u64t a1[2][4][4];
            #pragma unroll
            for (int g = 0; g < 4; g++) {
                u64t bp = lds64(&sB1[g * H1 + u01]);   // reload per step (saves regs)
                float blo, bhi; upk(bp, blo, bhi);
                u64t plo = pk2(blo, blo), phi = pk2(bhi, bhi);
                #pragma unroll
                for (int p = 0; p < 4; p++) { a1[0][g][p] = plo; a1[1][g][p] = phi; }
            }
            #pragma unroll
            for (int d = 0; d < DD; d++) {
                u64t wp[2][4];
                #pragma unroll
                for (int g = 0; g < 4; g++) {
                    u64t wv = lds64(&sW1T[d * G1 + g * H1 + u01]);
                    float wl, wh; upk(wv, wl, wh);
                    wp[0][g] = pk2(wl, wl); wp[1][g] = pk2(wh, wh);
                }
                #pragma unroll
                for (int p = 0; p < 4; p++) {
                    u64t xv = lds64(&sXw[d * XS + 2 * p]);
                    #pragma unroll
                    for (int g = 0; g < 4; g++) {
                        a1[0][g][p] = fma2(wp[0][g], xv, a1[0][g][p]);
                        a1[1][g][p] = fma2(wp[1][g], xv, a1[1][g][p]);
                    }
                }
            }
            #pragma unroll 2
            for (int k = 0; k < H1; k++) {
                u64t wp[2][4];
                #pragma unroll
                for (int g = 0; g < 4; g++) {
                    u64t wv = lds64(&sW1T[(DD + k) * G1 + g * H1 + u01]);
                    float wl, wh; upk(wv, wl, wh);
                    wp[0][g] = pk2(wl, wl); wp[1][g] = pk2(wh, wh);
                }
                #pragma unroll
                for (int p = 0; p < 4; p++) {
                    u64t hv = lds64(&sH1w[k * HS1 + 2 * p]);
                    #pragma unroll
                    for (int g = 0; g < 4; g++) {
                        a1[0][g][p] = fma2(wp[0][g], hv, a1[0][g][p]);
                        a1[1][g][p] = fma2(wp[1][g], hv, a1[1][g][p]);
                    }
                }
            }
            __syncwarp();                      // WAR on old h1

            // pointwise layer1 + write new h1
            #pragma unroll
            for (int u = 0; u < 2; u++) {
                #pragma unroll
                for (int p = 0; p < 4; p++) {
                    float gi[2], gf[2], gg[2], go[2], hh[2];
                    upk(a1[u][0][p], gi[0], gi[1]);
                    upk(a1[u][1][p], gf[0], gf[1]);
                    upk(a1[u][2][p], gg[0], gg[1]);
                    upk(a1[u][3][p], go[0], go[1]);
                    #pragma unroll
                    for (int s = 0; s < 2; s++) {
                        float ii = sig_h(gi[s]);
                        float ff = sig_h(gf[s]);
                        float g_ = tanha(gg[s]);
                        float oo = sig_h(go[s]);
                        float cc = ff * c1[u][2 * p + s] + ii * g_;
                        c1[u][2 * p + s] = cc;
                        hh[s] = oo * tanha(cc);
                    }
                    sts64(&sH1w[(u01 + u) * HS1 + 2 * p], pk2(hh[0], hh[1]));
                }
            }
            __syncwarp();                      // RAW: new h1 visible

            // ================= layer 2 gates =================
            u64t a2[2][4][2];
            #pragma unroll
            for (int g = 0; g < 4; g++) {
                u64t bp = lds64(&sB2[g * H2 + u02]);   // reload per step
                float blo, bhi; upk(bp, blo, bhi);
                u64t plo = pk2(blo, blo), phi = pk2(bhi, bhi);
                #pragma unroll
                for (int p = 0; p < 2; p++) { a2[0][g][p] = plo; a2[1][g][p] = phi; }
            }
            #pragma unroll 2
            for (int k = 0; k < H1; k++) {     // input = new h1
                u64t wp[2][4];
                #pragma unroll
                for (int g = 0; g < 4; g++) {
                    u64t wv = lds64(&sW2T[k * G2 + g * H2 + u02]);
                    float wl, wh; upk(wv, wl, wh);
                    wp[0][g] = pk2(wl, wl); wp[1][g] = pk2(wh, wh);
                }
                #pragma unroll
                for (int p = 0; p < 2; p++) {
                    u64t hv = lds64(&sH1w[k * HS1 + bh2 + 2 * p]);
                    #pragma unroll
                    for (int g = 0; g < 4; g++) {
                        a2[0][g][p] = fma2(wp[0][g], hv, a2[0][g][p]);
                        a2[1][g][p] = fma2(wp[1][g], hv, a2[1][g][p]);
                    }
                }
            }
            #pragma unroll 2
            for (int k = 0; k < H2; k++) {     // recurrent = old h2
                u64t wp[2][4];
                #pragma unroll
                for (int g = 0; g < 4; g++) {
                    u64t wv = lds64(&sW2T[(H1 + k) * G2 + g * H2 + u02]);
                    float wl, wh; upk(wv, wl, wh);
                    wp[0][g] = pk2(wl, wl); wp[1][g] = pk2(wh, wh);
                }
                #pragma unroll
                for (int p = 0; p < 2; p++) {
                    u64t hv = lds64(&sH2w[k * HS2 + bh2 + 2 * p]);
                    #pragma unroll
                    for (int g = 0; g < 4; g++) {
                        a2[0][g][p] = fma2(wp[0][g], hv, a2[0][g][p]);
                        a2[1][g][p] = fma2(wp[1][g], hv, a2[1][g][p]);
                    }
                }
            }
            __syncwarp();                      // WAR on old h2

            // pointwise layer2 + write new h2
            #pragma unroll
            for (int u = 0; u < 2; u++) {
                #pragma unroll
                for (int p = 0; p < 2; p++) {
                    float gi[2], gf[2], gg[2], go[2], hh[2];
                    upk(a2[u][0][p], gi[0], gi[1]);
                    upk(a2[u][1][p], gf[0], gf[1]);
                    upk(a2[u][2][p], gg[0], gg[1]);
                    upk(a2[u][3][p], go[0], go[1]);
                    #pragma unroll
                    for (int s = 0; s < 2; s++) {
                        float ii = sig_h(gi[s]);
                        float ff = sig_h(gf[s]);
                        float g_ = tanha(gg[s]);
                        float oo = sig_h(go[s]);
                        float cc = ff * c2[u][2 * p + s] + ii * g_;
                        c2[u][2 * p + s] = cc;
                        hh[s] = oo * tanha(cc);
                    }
                    sts64(&sH2w[(u02 + u) * HS2 + bh2 + 2 * p], pk2(hh[0], hh[1]));
                }
            }
            __syncwarp();                      // new h2 visible
        }

        // ================= head: dense(16)+relu -> dot(16)+sigmoid =============
        if (lane < TB) {
            const int b = lane;
            float hv[H2];
            #pragma unroll
            for (int k = 0; k < H2; k++) hv[k] = sH2w[k * HS2 + b];
            float o = __ldg(&bo[0]);
            #pragma unroll
            for (int j = 0; j < 16; j++) {
                float s = __ldg(&bd[j]);
                #pragma unroll
                for (int k = 0; k < H2; k++) s += hv[k] * __ldg(&Wd[j * H2 + k]);
                o += fmaxf(s, 0.0f) * __ldg(&Wo[j]);
            }
            out[tau * TB + b] = sigx(o);
        }
        __syncwarp();
    }
}

extern "C" void kernel_launch(void* const* d_in, const int* in_sizes, int n_in,
                              void* d_out, int out_size) {
    const float* x    = (const float*)d_in[0];
    const float* Wih1 = (const float*)d_in[1];
    const float* Whh1 = (const float*)d_in[2];
    const float* bih1 = (const float*)d_in[3];
    const float* bhh1 = (const float*)d_in[4];
    const float* Wih2 = (const float*)d_in[5];
    const float* Whh2 = (const float*)d_in[6];
    const float* bih2 = (const float*)d_in[7];
    const float* bhh2 = (const float*)d_in[8];
    const float* Wd   = (const float*)d_in[9];
    const float* bd   = (const float*)d_in[10];
    const float* Wo   = (const float*)d_in[11];
    const float* bo   = (const float*)d_in[12];
    float* out = (float*)d_out;

    static bool attr_set = false;
    if (!attr_set) {
        cudaFuncSetAttribute(momentum_lstm_kernel,
                             cudaFuncAttributeMaxDynamicSharedMemorySize, SMEM_BYTES);
        attr_set = true;
    }

    momentum_lstm_kernel<<<GRID, NT, SMEM_BYTES>>>(
        x, Wih1, Whh1, bih1, bhh1, Wih2, Whh2, bih2, bhh2, Wd, bd, Wo, bo, out);
}